// round 6
// baseline (speedup 1.0000x reference)
#include <cuda_runtime.h>
#include <math.h>

// Problem constants
#define H     1536
#define H3    4608          // 3*H
#define HV    128           // vocab
#define ML    128           // max_length
#define AROWS 129           // ML+1 attention rows
#define MPAD  132           // padded row stride for 129-wide matrices
#define GRID  148
#define BLOCK 1024

// ---------------- device scratch (no allocations allowed) ----------------
__device__ __align__(16) float g_encout[AROWS * H];   // encoder outputs (129 x 1536)
__device__ __align__(16) float g_gi[H3];              // Wih-side gate pre-activations (+bih)
__device__ __align__(16) float g_gh[H3];              // Whh-side gate pre-activations (+bhh)
__device__ __align__(16) float g_attnh[AROWS];        // attn h-half logits
__device__ __align__(16) float g_o[HV];               // output logits
__device__ __align__(16) float g_x[H];                // relu(comb) input to dec GRU
__device__ __align__(16) float g_M[H * MPAD];         // comb_W_ctx @ encout^T  (1536 x 129)
__device__ __align__(16) float g_attE[HV * MPAD];     // attn_W_emb @ emb_dec^T + attn_b
__device__ __align__(16) float g_combE[HV * H];       // comb_W_emb @ emb_dec^T + comb_b
__device__ unsigned g_bar;                            // grid barrier (monotonic)

// ---- grid barrier: release-add / acquire-poll (no CCTL.IVALL) ----
// Correct because every mutable cross-phase scratch READ below uses __ldcg
// (L2-direct); write-once tables are only read cold, so .ca is safe for them.
__device__ __forceinline__ void grid_sync() {
    __syncthreads();
    if (threadIdx.x == 0) {
        unsigned* p = &g_bar;
        unsigned old;
        asm volatile("atom.release.gpu.global.add.u32 %0, [%1], %2;"
                     : "=r"(old) : "l"(p), "r"(1u) : "memory");
        unsigned target = old - (old % GRID) + GRID;
        unsigned v;
        do {
            asm volatile("ld.acquire.gpu.global.u32 %0, [%1];"
                         : "=r"(v) : "l"(p) : "memory");
        } while ((int)(v - target) < 0);
    }
    __syncthreads();
}

// ---------------- warp helpers ----------------
__device__ __forceinline__ float wredu(float v) {
#pragma unroll
    for (int o = 16; o; o >>= 1) v += __shfl_xor_sync(0xffffffffu, v, o);
    return v;
}

__device__ __forceinline__ void wargmax(float& m, int& am) {
#pragma unroll
    for (int o = 16; o; o >>= 1) {
        float m2 = __shfl_xor_sync(0xffffffffu, m, o);
        int   a2 = __shfl_xor_sync(0xffffffffu, am, o);
        if (m2 > m || (m2 == m && a2 < am)) { m = m2; am = a2; }
    }
}

__device__ __forceinline__ float sigm(float x) { return 1.f / (1.f + expf(-x)); }

// dot of a global weight row with a SMEM-resident vector
__device__ __forceinline__ float dot1536s(const float* __restrict__ w,
                                          const float4* __restrict__ sx, int lane) {
    const float4* w4 = (const float4*)w;
    float s = 0.f;
#pragma unroll 4
    for (int i = 0; i < 12; i++) {
        float4 a = w4[lane + 32 * i];
        float4 b = sx[lane + 32 * i];
        s = fmaf(a.x, b.x, s); s = fmaf(a.y, b.y, s);
        s = fmaf(a.z, b.z, s); s = fmaf(a.w, b.w, s);
    }
    return s;
}

// three weight rows vs one SMEM vector (encoder gate triples)
__device__ __forceinline__ void dot3s(const float* __restrict__ w0,
                                      const float* __restrict__ w1,
                                      const float* __restrict__ w2,
                                      const float4* __restrict__ sx,
                                      int lane, float* r) {
    const float4* a0 = (const float4*)w0;
    const float4* a1 = (const float4*)w1;
    const float4* a2 = (const float4*)w2;
    float s0 = 0.f, s1 = 0.f, s2 = 0.f;
#pragma unroll 4
    for (int i = 0; i < 12; i++) {
        int idx = lane + 32 * i;
        float4 b = sx[idx];
        float4 a;
        a = a0[idx]; s0 = fmaf(a.x,b.x,s0); s0 = fmaf(a.y,b.y,s0); s0 = fmaf(a.z,b.z,s0); s0 = fmaf(a.w,b.w,s0);
        a = a1[idx]; s1 = fmaf(a.x,b.x,s1); s1 = fmaf(a.y,b.y,s1); s1 = fmaf(a.z,b.z,s1); s1 = fmaf(a.w,b.w,s1);
        a = a2[idx]; s2 = fmaf(a.x,b.x,s2); s2 = fmaf(a.y,b.y,s2); s2 = fmaf(a.z,b.z,s2); s2 = fmaf(a.w,b.w,s2);
    }
    r[0] = s0; r[1] = s1; r[2] = s2;
}

// one weight row vs 8 global vectors (precompute GEMMs; vectors L1-resident per tile)
__device__ __forceinline__ void dot8(const float* __restrict__ w,
                                     const float4* p0, const float4* p1,
                                     const float4* p2, const float4* p3,
                                     const float4* p4, const float4* p5,
                                     const float4* p6, const float4* p7,
                                     int lane, float* r) {
    const float4* w4 = (const float4*)w;
    float s0=0.f,s1=0.f,s2=0.f,s3=0.f,s4=0.f,s5=0.f,s6=0.f,s7=0.f;
#pragma unroll 2
    for (int i = 0; i < 12; i++) {
        int idx = lane + 32 * i;
        float4 a = w4[idx];
        float4 b;
        b = p0[idx]; s0 = fmaf(a.x,b.x,s0); s0 = fmaf(a.y,b.y,s0); s0 = fmaf(a.z,b.z,s0); s0 = fmaf(a.w,b.w,s0);
        b = p1[idx]; s1 = fmaf(a.x,b.x,s1); s1 = fmaf(a.y,b.y,s1); s1 = fmaf(a.z,b.z,s1); s1 = fmaf(a.w,b.w,s1);
        b = p2[idx]; s2 = fmaf(a.x,b.x,s2); s2 = fmaf(a.y,b.y,s2); s2 = fmaf(a.z,b.z,s2); s2 = fmaf(a.w,b.w,s2);
        b = p3[idx]; s3 = fmaf(a.x,b.x,s3); s3 = fmaf(a.y,b.y,s3); s3 = fmaf(a.z,b.z,s3); s3 = fmaf(a.w,b.w,s3);
        b = p4[idx]; s4 = fmaf(a.x,b.x,s4); s4 = fmaf(a.y,b.y,s4); s4 = fmaf(a.z,b.z,s4); s4 = fmaf(a.w,b.w,s4);
        b = p5[idx]; s5 = fmaf(a.x,b.x,s5); s5 = fmaf(a.y,b.y,s5); s5 = fmaf(a.z,b.z,s5); s5 = fmaf(a.w,b.w,s5);
        b = p6[idx]; s6 = fmaf(a.x,b.x,s6); s6 = fmaf(a.y,b.y,s6); s6 = fmaf(a.z,b.z,s6); s6 = fmaf(a.w,b.w,s6);
        b = p7[idx]; s7 = fmaf(a.x,b.x,s7); s7 = fmaf(a.y,b.y,s7); s7 = fmaf(a.z,b.z,s7); s7 = fmaf(a.w,b.w,s7);
    }
    r[0]=s0; r[1]=s1; r[2]=s2; r[3]=s3; r[4]=s4; r[5]=s5; r[6]=s6; r[7]=s7;
}

// ---------------- persistent kernel ----------------
__global__ __launch_bounds__(BLOCK, 1)
void seq2seq_kernel(const int* __restrict__ input, int L,
                    const float* __restrict__ emb_enc,
                    const float* __restrict__ enc_Wih, const float* __restrict__ enc_Whh,
                    const float* __restrict__ enc_bih, const float* __restrict__ enc_bhh,
                    const float* __restrict__ emb_dec,
                    const float* __restrict__ attn_W, const float* __restrict__ attn_b,
                    const float* __restrict__ comb_W, const float* __restrict__ comb_b,
                    const float* __restrict__ dec_Wih, const float* __restrict__ dec_Whh,
                    const float* __restrict__ dec_bih, const float* __restrict__ dec_bhh,
                    const float* __restrict__ out_W, const float* __restrict__ out_b,
                    float* __restrict__ out, int write_tok)
{
    const int tid  = threadIdx.x;
    const int lane = tid & 31;
    const int wid  = tid >> 5;
    const int b    = blockIdx.x;
    const int WGID = wid * GRID + b;

    __shared__ __align__(16) float s_hold[H];   // current hidden state (per block)
    __shared__ __align__(16) float s_x[H];      // staged input vector
    __shared__ float s_w[AROWS];
    __shared__ float s_red[32];
    __shared__ float s_S, s_lse;
    __shared__ int   s_tok;

    // ---- init: zero encout tail + h0 in smem ----
    {
        int gt = b * BLOCK + tid, NT = GRID * BLOCK;
        for (int i = L * H + gt; i < AROWS * H; i += NT) g_encout[i] = 0.f;
        for (int i = tid; i < H; i += BLOCK) s_hold[i] = 0.f;
    }

    // ---- P_E: attE/combE = [attn_W_e; comb_W_e] @ emb_dec^T + bias ----
    // Tiled over 8 emb vectors so each SM's L1 serves the vector side.
    {
        int r = WGID;
        const float* w = attn_W; float bias = 0.f; int rc = 0; bool isA = true;
        bool valid = (r < AROWS + H);
        if (r < AROWS)      { w = attn_W + r * (2 * H); bias = attn_b[r]; }
        else if (valid)     { rc = r - AROWS; w = comb_W + rc * (2 * H); bias = comb_b[rc]; isA = false; }
        const float4* E4 = (const float4*)emb_dec;
        for (int tile = 0; tile < HV / 8; tile++) {
            if (valid) {
                int v0 = tile * 8;
                float s[8];
                dot8(w, E4 + (v0+0)*384, E4 + (v0+1)*384, E4 + (v0+2)*384, E4 + (v0+3)*384,
                        E4 + (v0+4)*384, E4 + (v0+5)*384, E4 + (v0+6)*384, E4 + (v0+7)*384,
                     lane, s);
#pragma unroll
                for (int q = 0; q < 8; q++) s[q] = wredu(s[q]);
                if (lane == 0) {
#pragma unroll
                    for (int q = 0; q < 8; q++) {
                        if (isA) g_attE[(v0+q) * MPAD + r]      = s[q] + bias;
                        else     g_combE[(v0+q) * H + rc]       = s[q] + bias;
                    }
                }
            }
            __syncthreads();
        }
    }
    // (published by the encoder's first grid_sync; read only in the decoder)

    // =========================== ENCODER ===========================
    for (int t = 0; ; t++) {
        if (t > 0) {
            // combine (redundant per block) -> s_hold; block0 also emits encout row
            for (int i = tid; i < H; i += BLOCK) {
                float rr = sigm(__ldcg(&g_gi[i])          + __ldcg(&g_gh[i]));
                float zz = sigm(__ldcg(&g_gi[H + i])      + __ldcg(&g_gh[H + i]));
                float nn = tanhf(__ldcg(&g_gi[2 * H + i]) + rr * __ldcg(&g_gh[2 * H + i]));
                float hv = (1.f - zz) * nn + zz * s_hold[i];
                s_hold[i] = hv;
                if (b == 0) g_encout[(t - 1) * H + i] = hv;
            }
            __syncthreads();
        }
        if (t >= L) break;
        // stage embedding
        {
            int tk = __ldg(&input[t]);
            const float4* e4 = (const float4*)(emb_enc + tk * H);
            if (tid < 384) ((float4*)s_x)[tid] = e4[tid];
            __syncthreads();
        }
        // 3072 balanced triple-dot tasks
        {
            int u = WGID;
            if (u < H) {
                float r3[3];
                dot3s(enc_Wih + u * H, enc_Wih + (H + u) * H, enc_Wih + (2 * H + u) * H,
                      (const float4*)s_x, lane, r3);
                r3[0] = wredu(r3[0]); r3[1] = wredu(r3[1]); r3[2] = wredu(r3[2]);
                if (lane == 0) {
                    g_gi[u]         = r3[0] + enc_bih[u];
                    g_gi[H + u]     = r3[1] + enc_bih[H + u];
                    g_gi[2 * H + u] = r3[2] + enc_bih[2 * H + u];
                }
            } else if (u < 2 * H) {
                int j = u - H;
                float r3[3];
                dot3s(enc_Whh + j * H, enc_Whh + (H + j) * H, enc_Whh + (2 * H + j) * H,
                      (const float4*)s_hold, lane, r3);
                r3[0] = wredu(r3[0]); r3[1] = wredu(r3[1]); r3[2] = wredu(r3[2]);
                if (lane == 0) {
                    g_gh[j]         = r3[0] + enc_bhh[j];
                    g_gh[H + j]     = r3[1] + enc_bhh[H + j];
                    g_gh[2 * H + j] = r3[2] + enc_bhh[2 * H + j];
                }
            }
        }
        grid_sync();
    }
    grid_sync();   // publish block0's encoder-output writes before P_M

    // ---- P_M: M[i][k] = comb_W_ctx[i,:] . encout[k,:]  (tiled over 8 enc vecs) ----
    {
        int r = WGID;
        const float* w = (r < H) ? comb_W + r * (2 * H) + H : comb_W;
        const float4* EO = (const float4*)g_encout;
        for (int tile = 0; tile < 17; tile++) {
            if (r < H) {
                int k0 = tile * 8;
                float s[8];
                dot8(w, EO + min(k0+0, AROWS-1)*384, EO + min(k0+1, AROWS-1)*384,
                        EO + min(k0+2, AROWS-1)*384, EO + min(k0+3, AROWS-1)*384,
                        EO + min(k0+4, AROWS-1)*384, EO + min(k0+5, AROWS-1)*384,
                        EO + min(k0+6, AROWS-1)*384, EO + min(k0+7, AROWS-1)*384,
                     lane, s);
#pragma unroll
                for (int q = 0; q < 8; q++) s[q] = wredu(s[q]);
                if (lane == 0) {
#pragma unroll
                    for (int q = 0; q < 8; q++)
                        if (k0 + q < AROWS) g_M[r * MPAD + k0 + q] = s[q];
                }
            }
            __syncthreads();
        }
    }
    // published by step-0 P1's grid_sync (read first in step-0 P2)

    // =========================== DECODER ===========================
    for (int t = 0; t < ML; t++) {
        if (t > 0) {
            // GRU combine (redundant per block) -> s_hold = h(t)
            for (int i = tid; i < H; i += BLOCK) {
                float rr = sigm(__ldcg(&g_gi[i])          + __ldcg(&g_gh[i]));
                float zz = sigm(__ldcg(&g_gi[H + i])      + __ldcg(&g_gh[H + i]));
                float nn = tanhf(__ldcg(&g_gi[2 * H + i]) + rr * __ldcg(&g_gh[2 * H + i]));
                s_hold[i] = (1.f - zz) * nn + zz * s_hold[i];
            }
            __syncthreads();
        }

        // --- P1: exactly one row per warp (4608 Whh + 128 out) + coop attn row ---
        {
            int r = b + GRID * wid;           // 0..4735
            if (r < H3) {
                float s = wredu(dot1536s(dec_Whh + r * H, (const float4*)s_hold, lane));
                if (lane == 0) g_gh[r] = s + dec_bhh[r];
            } else {
                int v = r - H3;               // 0..127
                float s = wredu(dot1536s(out_W + v * H, (const float4*)s_hold, lane));
                if (lane == 0) g_o[v] = s + out_b[v];
            }
            if (b < AROWS) {                  // block-cooperative attn_h row b
                const float4* w4 = (const float4*)(attn_W + b * (2 * H) + H);
                float p = 0.f;
                if (tid < 384) {
                    float4 a = w4[tid];
                    float4 c = ((const float4*)s_hold)[tid];
                    p = a.x*c.x + a.y*c.y + a.z*c.z + a.w*c.w;
                }
                p = wredu(p);
                if (lane == 0) s_red[wid] = p;
                __syncthreads();
                if (wid == 0) {
                    float v2 = s_red[lane];
                    v2 = wredu(v2);
                    if (lane == 0) g_attnh[b] = v2;
                }
            }
        }
        grid_sync();

        // --- P2: token select, emit row t-1, softmax weights, x rows ---
        if (wid == 0) {
            int tok; float lse;
            if (t == 0) { tok = 0; lse = 0.f; }
            else {
                float m = -1e30f; int am = HV;
                for (int v = lane; v < HV; v += 32) {
                    float ov = __ldcg(&g_o[v]);
                    if (ov > m) { m = ov; am = v; }
                }
                wargmax(m, am);
                float e = 0.f;
                for (int v = lane; v < HV; v += 32) e += expf(__ldcg(&g_o[v]) - m);
                e = wredu(e);
                lse = m + logf(e);
                tok = am;
            }
            if (lane == 0) { s_tok = tok; s_lse = lse; }
        }
        __syncthreads();
        const int tok = s_tok;
        if (t > 0 && b == 0 && wid == 1) {
            for (int v = lane; v < HV; v += 32) out[(t - 1) * HV + v] = __ldcg(&g_o[v]) - s_lse;
            if (lane == 0 && write_tok) out[ML * HV + (t - 1)] = (float)tok;
        }
        if (wid == 0) {
            const float* aE = g_attE + tok * MPAD;     // write-once table: .ca safe
            float m = -1e30f;
            for (int k = lane; k < AROWS; k += 32) m = fmaxf(m, aE[k] + __ldcg(&g_attnh[k]));
#pragma unroll
            for (int o = 16; o; o >>= 1) m = fmaxf(m, __shfl_xor_sync(0xffffffffu, m, o));
            float ssum = 0.f;
            for (int k = lane; k < AROWS; k += 32) {
                float e = expf(aE[k] + __ldcg(&g_attnh[k]) - m);
                s_w[k] = e;
                ssum += e;
            }
            ssum = wredu(ssum);
            if (lane == 0) s_S = ssum;
        }
        __syncthreads();
        {
            const float invS = 1.f / s_S;
            const float* cE = g_combE + tok * H;       // write-once: .ca safe
            int i = WGID;
            if (i < H) {
                const float* Mr = g_M + i * MPAD;      // write-once: .ca safe
                float s = 0.f;
                for (int k = lane; k < AROWS; k += 32) s = fmaf(s_w[k], Mr[k], s);
                s = wredu(s);
                if (lane == 0) g_x[i] = fmaxf(0.f, cE[i] + s * invS);
            }
        }
        grid_sync();

        // --- P3: stage x; 4608 balanced single-dot tasks -> g_gi ---
        {
            if (tid < 384) ((float4*)s_x)[tid] = __ldcg(((const float4*)g_x) + tid);
            __syncthreads();
            int j = WGID;
            if (j < H3) {
                float s = wredu(dot1536s(dec_Wih + j * H, (const float4*)s_x, lane));
                if (lane == 0) g_gi[j] = s + dec_bih[j];
            }
        }
        grid_sync();
    }

    // ---- epilogue: final combine + last logits row ----
    for (int i = tid; i < H; i += BLOCK) {
        float rr = sigm(__ldcg(&g_gi[i])          + __ldcg(&g_gh[i]));
        float zz = sigm(__ldcg(&g_gi[H + i])      + __ldcg(&g_gh[H + i]));
        float nn = tanhf(__ldcg(&g_gi[2 * H + i]) + rr * __ldcg(&g_gh[2 * H + i]));
        s_hold[i] = (1.f - zz) * nn + zz * s_hold[i];
    }
    __syncthreads();
    {
        int v = WGID;
        if (v < HV) {
            float s = wredu(dot1536s(out_W + v * H, (const float4*)s_hold, lane));
            if (lane == 0) g_o[v] = s + out_b[v];
        }
    }
    grid_sync();

    if (b == 0 && wid == 0) {
        float m = -1e30f; int am = HV;
        for (int v = lane; v < HV; v += 32) {
            float ov = __ldcg(&g_o[v]);
            if (ov > m) { m = ov; am = v; }
        }
        wargmax(m, am);
        float e = 0.f;
        for (int v = lane; v < HV; v += 32) e += expf(__ldcg(&g_o[v]) - m);
        e = wredu(e);
        float lse = m + logf(e);
        for (int v = lane; v < HV; v += 32) out[(ML - 1) * HV + v] = __ldcg(&g_o[v]) - lse;
        if (lane == 0 && write_tok) out[ML * HV + (ML - 1)] = (float)am;
    }
}

// ---------------- launch ----------------
extern "C" void kernel_launch(void* const* d_in, const int* in_sizes, int n_in,
                              void* d_out, int out_size) {
    const int*   input   = (const int*)  d_in[0];
    const int    L       = in_sizes[0];
    // d_in[1] = max_length scalar (compile-time ML=128)
    const float* emb_enc = (const float*)d_in[2];
    const float* enc_Wih = (const float*)d_in[3];
    const float* enc_Whh = (const float*)d_in[4];
    const float* enc_bih = (const float*)d_in[5];
    const float* enc_bhh = (const float*)d_in[6];
    const float* emb_dec = (const float*)d_in[7];
    const float* attn_W  = (const float*)d_in[8];
    const float* attn_b  = (const float*)d_in[9];
    const float* comb_W  = (const float*)d_in[10];
    const float* comb_b  = (const float*)d_in[11];
    const float* dec_Wih = (const float*)d_in[12];
    const float* dec_Whh = (const float*)d_in[13];
    const float* dec_bih = (const float*)d_in[14];
    const float* dec_bhh = (const float*)d_in[15];
    const float* out_W   = (const float*)d_in[16];
    const float* out_b   = (const float*)d_in[17];

    int write_tok = (out_size >= ML * HV + ML) ? 1 : 0;

    seq2seq_kernel<<<GRID, BLOCK>>>(input, L, emb_enc,
                                    enc_Wih, enc_Whh, enc_bih, enc_bhh,
                                    emb_dec, attn_W, attn_b, comb_W, comb_b,
                                    dec_Wih, dec_Whh, dec_bih, dec_bhh,
                                    out_W, out_b,
                                    (float*)d_out, write_tok);
}